// round 2
// baseline (speedup 1.0000x reference)
#include <cuda_runtime.h>
#include <cuda_fp16.h>
#include <stdint.h>

#define TT 256
#define BB 128
#define VV 256
#define EE 512
#define NH 1024
#define TB (TT*BB)          // 32768
#define G4 (4*NH)           // 4096

// ---------------- static device scratch ----------------
__device__ __align__(16) __half g_inph[(size_t)TB*VV];
__device__ __align__(16) __half g_embs[(size_t)TB*EE];
__device__ __align__(16) float  g_X[(size_t)TB*G4];
__device__ __align__(16) __half g_H0[(size_t)TB*NH];
__device__ __align__(16) __half g_H1[(size_t)TB*NH];
__device__ __align__(16) __half g_hzero[BB*NH];          // zero-initialized, never written
__device__ __align__(16) float  g_c[2*BB*NH];
__device__ __align__(16) __half g_embT[EE*VV];           // [512][256]
__device__ __align__(16) __half g_w0xT[(size_t)G4*EE];   // [4096][512]
__device__ __align__(16) __half g_w0hT[(size_t)G4*NH];   // [4096][1024]
__device__ __align__(16) __half g_w1xT[(size_t)G4*NH];   // [4096][1024]
__device__ __align__(16) __half g_w1hT[(size_t)G4*NH];   // [4096][1024]
__device__ __align__(16) __half g_owT[VV*NH];            // [256][1024]

// ---------------- helpers ----------------
__device__ __forceinline__ void mma16(float d[4], const unsigned a[4], const unsigned b[2]) {
    asm volatile(
        "mma.sync.aligned.m16n8k16.row.col.f32.f16.f16.f32 "
        "{%0,%1,%2,%3}, {%4,%5,%6,%7}, {%8,%9}, {%0,%1,%2,%3};\n"
        : "+f"(d[0]), "+f"(d[1]), "+f"(d[2]), "+f"(d[3])
        : "r"(a[0]), "r"(a[1]), "r"(a[2]), "r"(a[3]), "r"(b[0]), "r"(b[1]));
}
__device__ __forceinline__ void cstore(__half* C, size_t i, float v) { C[i] = __float2half(v); }
__device__ __forceinline__ void cstore(float*  C, size_t i, float v) { C[i] = v; }
__device__ __forceinline__ float sigf(float x) { return 1.f / (1.f + __expf(-x)); }

__global__ void zero_f(float* __restrict__ p, int n) {
    for (int i = blockIdx.x * blockDim.x + threadIdx.x; i < n; i += gridDim.x * blockDim.x)
        p[i] = 0.f;
}
__global__ void f2h_kernel(const float* __restrict__ s, __half* __restrict__ d, int n) {
    for (int i = blockIdx.x * blockDim.x + threadIdx.x; i < n; i += gridDim.x * blockDim.x)
        d[i] = __float2half(s[i]);
}
// src fp32 [K][N] (row stride lds) -> dst fp16 [N][K]
__global__ void transpose_cvt(const float* __restrict__ src, int lds,
                              __half* __restrict__ dst, int K, int N) {
    __shared__ float tile[32][33];
    int kb = blockIdx.x * 32, nb = blockIdx.y * 32;
    #pragma unroll
    for (int i = threadIdx.y; i < 32; i += 8) {
        int k = kb + i, n = nb + threadIdx.x;
        tile[i][threadIdx.x] = (k < K && n < N) ? src[(size_t)k * lds + n] : 0.f;
    }
    __syncthreads();
    #pragma unroll
    for (int i = threadIdx.y; i < 32; i += 8) {
        int n = nb + i, k = kb + threadIdx.x;
        if (n < N && k < K) dst[(size_t)n * K + k] = __float2half(tile[threadIdx.x][i]);
    }
}

// ---------------- generic fp16 GEMM: C[M,N] = A[M,K] @ Bt[N,K]^T (+bias) ----------------
// CTA tile 128x64, K-tile 32, 256 threads (8 warps 4x2), warp tile 32x32.
template <typename TOUT>
__global__ void __launch_bounds__(256) gemm16(
    const __half* __restrict__ A, int lda,
    const __half* __restrict__ Bt,
    TOUT* __restrict__ C, int ldc,
    const float* __restrict__ bias,
    int M, int N, int K)
{
    __shared__ __half As[2][128][40];
    __shared__ __half Bs[2][64][40];

    const int tid = threadIdx.x;
    const int bm = blockIdx.y * 128, bn = blockIdx.x * 64;
    const int wid = tid >> 5, lane = tid & 31;
    const int wr = (wid >> 1) * 32, wc = (wid & 1) * 32;
    const int r = lane >> 2, cl = lane & 3;
    const int ar0 = tid >> 2, aq = tid & 3;

    uint4 ga0, ga1, gb;
    float acc[2][4][4];
    #pragma unroll
    for (int i = 0; i < 2; ++i)
        #pragma unroll
        for (int j = 0; j < 4; ++j)
            #pragma unroll
            for (int k = 0; k < 4; ++k) acc[i][j][k] = 0.f;

    auto loadG = [&](int kt) {
        const __half* Ab = A + (size_t)bm * lda + kt * 32;
        ga0 = *(const uint4*)(Ab + (size_t)ar0 * lda + aq * 8);
        ga1 = *(const uint4*)(Ab + (size_t)(ar0 + 64) * lda + aq * 8);
        gb  = *(const uint4*)(Bt + (size_t)(bn + ar0) * K + kt * 32 + aq * 8);
    };
    auto storeS = [&](int buf) {
        *(uint4*)&As[buf][ar0][aq * 8]      = ga0;
        *(uint4*)&As[buf][ar0 + 64][aq * 8] = ga1;
        *(uint4*)&Bs[buf][ar0][aq * 8]      = gb;
    };

    loadG(0); storeS(0); __syncthreads();

    const int ktiles = K >> 5;
    for (int kt = 0; kt < ktiles; ++kt) {
        const int buf = kt & 1;
        if (kt + 1 < ktiles) loadG(kt + 1);

        #pragma unroll
        for (int ks = 0; ks < 2; ++ks) {
            const int k0 = ks * 16;
            unsigned af[2][4], bf[4][2];
            #pragma unroll
            for (int mt = 0; mt < 2; ++mt) {
                af[mt][0] = *(const unsigned*)&As[buf][wr + mt * 16 + r    ][k0 + 2 * cl];
                af[mt][1] = *(const unsigned*)&As[buf][wr + mt * 16 + r + 8][k0 + 2 * cl];
                af[mt][2] = *(const unsigned*)&As[buf][wr + mt * 16 + r    ][k0 + 2 * cl + 8];
                af[mt][3] = *(const unsigned*)&As[buf][wr + mt * 16 + r + 8][k0 + 2 * cl + 8];
            }
            #pragma unroll
            for (int nt = 0; nt < 4; ++nt) {
                bf[nt][0] = *(const unsigned*)&Bs[buf][wc + nt * 8 + r][k0 + 2 * cl];
                bf[nt][1] = *(const unsigned*)&Bs[buf][wc + nt * 8 + r][k0 + 2 * cl + 8];
            }
            #pragma unroll
            for (int mt = 0; mt < 2; ++mt)
                #pragma unroll
                for (int nt = 0; nt < 4; ++nt)
                    mma16(acc[mt][nt], af[mt], bf[nt]);
        }
        if (kt + 1 < ktiles) storeS((kt + 1) & 1);
        __syncthreads();
    }

    #pragma unroll
    for (int mt = 0; mt < 2; ++mt)
        #pragma unroll
        for (int nt = 0; nt < 4; ++nt) {
            const int row = bm + wr + mt * 16 + r;
            const int col = bn + wc + nt * 8 + 2 * cl;
            const float b0 = bias ? bias[col]     : 0.f;
            const float b1 = bias ? bias[col + 1] : 0.f;
            cstore(C, (size_t)row * ldc + col,           acc[mt][nt][0] + b0);
            cstore(C, (size_t)row * ldc + col + 1,       acc[mt][nt][1] + b1);
            cstore(C, (size_t)(row + 8) * ldc + col,     acc[mt][nt][2] + b0);
            cstore(C, (size_t)(row + 8) * ldc + col + 1, acc[mt][nt][3] + b1);
        }
}

// ---------------- LSTM step: lin = Xt + hprev@Wh; gates; update c,h ----------------
// CTA bx handles hidden cols [bx*8, bx*8+8) across 4 gates: GEMM M=128, N=32, K=1024.
__global__ void __launch_bounds__(256) lstm_step(
    const __half* __restrict__ hprev,   // [128][1024]
    const __half* __restrict__ WhT,     // [4096][1024]
    const float*  __restrict__ Xt,      // [128][4096]
    float* __restrict__ cst,            // [128][1024]
    __half* __restrict__ hout)          // [128][1024]
{
    __shared__ __half As[2][128][40];
    __shared__ __half Bs[2][32][40];
    __shared__ float  Ls[128][36];

    const int tid = threadIdx.x, lane = tid & 31, wid = tid >> 5;
    const int r = lane >> 2, cl = lane & 3;
    const int bx = blockIdx.x;
    const int wr = wid * 16;
    const int ar0 = tid >> 2, aq = tid & 3;

    const bool bldr = (tid < 128);
    size_t brow_off = 0;
    if (bldr) {
        const int nrow = tid >> 2;
        const int g = nrow >> 3, j = nrow & 7, bq = tid & 3;
        brow_off = (size_t)(g * 1024 + bx * 8 + j) * 1024 + bq * 8;
    }

    uint4 ga0, ga1, gb;
    float acc[4][4];
    #pragma unroll
    for (int i = 0; i < 4; ++i)
        #pragma unroll
        for (int j = 0; j < 4; ++j) acc[i][j] = 0.f;

    auto loadG = [&](int kt) {
        ga0 = *(const uint4*)(hprev + (size_t)ar0 * 1024 + kt * 32 + aq * 8);
        ga1 = *(const uint4*)(hprev + (size_t)(ar0 + 64) * 1024 + kt * 32 + aq * 8);
        if (bldr) gb = *(const uint4*)(WhT + brow_off + (size_t)kt * 32);
    };
    auto storeS = [&](int buf) {
        *(uint4*)&As[buf][ar0][aq * 8]      = ga0;
        *(uint4*)&As[buf][ar0 + 64][aq * 8] = ga1;
        if (bldr) *(uint4*)&Bs[buf][tid >> 2][(tid & 3) * 8] = gb;
    };

    loadG(0); storeS(0); __syncthreads();

    #pragma unroll 1
    for (int kt = 0; kt < 32; ++kt) {
        const int buf = kt & 1;
        if (kt < 31) loadG(kt + 1);

        #pragma unroll
        for (int ks = 0; ks < 2; ++ks) {
            const int k0 = ks * 16;
            unsigned af[4];
            af[0] = *(const unsigned*)&As[buf][wr + r    ][k0 + 2 * cl];
            af[1] = *(const unsigned*)&As[buf][wr + r + 8][k0 + 2 * cl];
            af[2] = *(const unsigned*)&As[buf][wr + r    ][k0 + 2 * cl + 8];
            af[3] = *(const unsigned*)&As[buf][wr + r + 8][k0 + 2 * cl + 8];
            #pragma unroll
            for (int nt = 0; nt < 4; ++nt) {
                unsigned bf[2];
                bf[0] = *(const unsigned*)&Bs[buf][nt * 8 + r][k0 + 2 * cl];
                bf[1] = *(const unsigned*)&Bs[buf][nt * 8 + r][k0 + 2 * cl + 8];
                mma16(acc[nt], af, bf);
            }
        }
        if (kt < 31) storeS((kt + 1) & 1);
        __syncthreads();
    }

    #pragma unroll
    for (int nt = 0; nt < 4; ++nt) {
        const int row = wr + r, col = nt * 8 + 2 * cl;
        Ls[row][col]         = acc[nt][0];
        Ls[row][col + 1]     = acc[nt][1];
        Ls[row + 8][col]     = acc[nt][2];
        Ls[row + 8][col + 1] = acc[nt][3];
    }
    __syncthreads();

    #pragma unroll
    for (int it = 0; it < 4; ++it) {
        const int flat = tid + it * 256;          // 0..1023
        const int b = flat >> 3, jj = flat & 7;
        const int col = bx * 8 + jj;
        const float* xb = Xt + (size_t)b * 4096;
        const float lf = Ls[b][jj]      + xb[col];
        const float li = Ls[b][8 + jj]  + xb[1024 + col];
        const float lo = Ls[b][16 + jj] + xb[2048 + col];
        const float lg = Ls[b][24 + jj] + xb[3072 + col];
        const float fg = sigf(lf);
        const float ig = sigf(li);
        const float og = sigf(lo);
        const float gg = tanhf(lg);
        const float cN = fg * cst[b * 1024 + col] + ig * gg;
        cst[b * 1024 + col]  = cN;
        hout[b * 1024 + col] = __float2half(og * tanhf(cN));
    }
}

// ---------------- launch ----------------
extern "C" void kernel_launch(void* const* d_in, const int* in_sizes, int n_in,
                              void* d_out, int out_size) {
    (void)in_sizes; (void)n_in; (void)out_size;
    const float* inputs = (const float*)d_in[0];
    const float* emb    = (const float*)d_in[1];
    const float* w0     = (const float*)d_in[2];
    const float* b0     = (const float*)d_in[3];
    const float* w1     = (const float*)d_in[4];
    const float* b1     = (const float*)d_in[5];
    const float* outw   = (const float*)d_in[6];
    const float* outb   = (const float*)d_in[7];
    float* out = (float*)d_out;

    __half *inph, *embs, *H0, *H1, *hzero, *embT, *w0xT, *w0hT, *w1xT, *w1hT, *owT;
    float *X, *cbuf;
    cudaGetSymbolAddress((void**)&inph,  g_inph);
    cudaGetSymbolAddress((void**)&embs,  g_embs);
    cudaGetSymbolAddress((void**)&X,     g_X);
    cudaGetSymbolAddress((void**)&H0,    g_H0);
    cudaGetSymbolAddress((void**)&H1,    g_H1);
    cudaGetSymbolAddress((void**)&hzero, g_hzero);
    cudaGetSymbolAddress((void**)&cbuf,  g_c);
    cudaGetSymbolAddress((void**)&embT,  g_embT);
    cudaGetSymbolAddress((void**)&w0xT,  g_w0xT);
    cudaGetSymbolAddress((void**)&w0hT,  g_w0hT);
    cudaGetSymbolAddress((void**)&w1xT,  g_w1xT);
    cudaGetSymbolAddress((void**)&w1hT,  g_w1hT);
    cudaGetSymbolAddress((void**)&owT,   g_owT);

    // prep: fp16 inputs + transposed fp16 weights
    f2h_kernel<<<1024, 256>>>(inputs, inph, TB * VV);
    {
        dim3 blk(32, 8);
        transpose_cvt<<<dim3(VV/32,  EE/32), blk>>>(emb,              EE,  embT, VV,  EE);
        transpose_cvt<<<dim3(EE/32,  G4/32), blk>>>(w0,               G4,  w0xT, EE,  G4);
        transpose_cvt<<<dim3(NH/32,  G4/32), blk>>>(w0 + (size_t)EE*G4, G4, w0hT, NH, G4);
        transpose_cvt<<<dim3(NH/32,  G4/32), blk>>>(w1,               G4,  w1xT, NH,  G4);
        transpose_cvt<<<dim3(NH/32,  G4/32), blk>>>(w1 + (size_t)NH*G4, G4, w1hT, NH, G4);
        transpose_cvt<<<dim3(NH/32,  VV/32), blk>>>(outw,             VV,  owT,  NH,  VV);
    }

    // embs = inputs @ emb   [32768,512]
    gemm16<__half><<<dim3(EE/64, TB/128), 256>>>(inph, VV, embT, embs, EE, nullptr, TB, EE, VV);
    // X = embs @ W0x + b0   [32768,4096]
    gemm16<float><<<dim3(G4/64, TB/128), 256>>>(embs, EE, w0xT, X, G4, b0, TB, G4, EE);

    zero_f<<<256, 256>>>(cbuf, 2 * BB * NH);

    // layer 0
    for (int t = 0; t < TT; ++t) {
        const __half* hp = (t == 0) ? hzero : H0 + (size_t)(t - 1) * BB * NH;
        lstm_step<<<128, 256>>>(hp, w0hT, X + (size_t)t * BB * G4, cbuf,
                                H0 + (size_t)t * BB * NH);
    }
    // X = H0 @ W1x + b1
    gemm16<float><<<dim3(G4/64, TB/128), 256>>>(H0, NH, w1xT, X, G4, b1, TB, G4, NH);
    // layer 1
    for (int t = 0; t < TT; ++t) {
        const __half* hp = (t == 0) ? hzero : H1 + (size_t)(t - 1) * BB * NH;
        lstm_step<<<128, 256>>>(hp, w1hT, X + (size_t)t * BB * G4, cbuf + BB * NH,
                                H1 + (size_t)t * BB * NH);
    }
    // logits = H1 @ out_w + out_b  [32768,256]
    gemm16<float><<<dim3(VV/64, TB/128), 256>>>(H1, NH, owT, out, VV, outb, TB, VV, NH);
}

// round 3
// speedup vs baseline: 1.5857x; 1.5857x over previous
#include <cuda_runtime.h>
#include <cuda_fp16.h>
#include <stdint.h>

#define TT 256
#define BB 128
#define VV 256
#define EE 512
#define NH 1024
#define TB (TT*BB)          // 32768
#define G4 (4*NH)           // 4096

// ---------------- static device scratch ----------------
__device__ __align__(16) __half g_inph[(size_t)TB*VV];
__device__ __align__(16) __half g_embs[(size_t)TB*EE];
__device__ __align__(16) float  g_X[(size_t)TB*G4];
__device__ __align__(16) __half g_H0[(size_t)TB*NH];
__device__ __align__(16) __half g_H1[(size_t)TB*NH];
__device__ __align__(16) __half g_embT[EE*VV];           // [512][256]
__device__ __align__(16) __half g_w0xT[(size_t)G4*EE];   // [4096][512]
__device__ __align__(16) __half g_w0hT[(size_t)G4*NH];   // [4096][1024]
__device__ __align__(16) __half g_w1xT[(size_t)G4*NH];   // [4096][1024]
__device__ __align__(16) __half g_w1hT[(size_t)G4*NH];   // [4096][1024]
__device__ __align__(16) __half g_owT[VV*NH];            // [256][1024]
__device__ int g_ctr[2];

// ---------------- helpers ----------------
__device__ __forceinline__ void mma16(float d[4], const unsigned a[4], const unsigned b[2]) {
    asm volatile(
        "mma.sync.aligned.m16n8k16.row.col.f32.f16.f16.f32 "
        "{%0,%1,%2,%3}, {%4,%5,%6,%7}, {%8,%9}, {%0,%1,%2,%3};\n"
        : "+f"(d[0]), "+f"(d[1]), "+f"(d[2]), "+f"(d[3])
        : "r"(a[0]), "r"(a[1]), "r"(a[2]), "r"(a[3]), "r"(b[0]), "r"(b[1]));
}
__device__ __forceinline__ void cpa16(__half* dst, const __half* src) {
    unsigned d = (unsigned)__cvta_generic_to_shared(dst);
    asm volatile("cp.async.cg.shared.global [%0], [%1], 16;\n" :: "r"(d), "l"(src));
}
#define CPA_COMMIT() asm volatile("cp.async.commit_group;\n" ::: "memory")
template <int N> __device__ __forceinline__ void cpa_wait() {
    asm volatile("cp.async.wait_group %0;\n" :: "n"(N) : "memory");
}
__device__ __forceinline__ void cstore(__half* C, size_t i, float v) { C[i] = __float2half(v); }
__device__ __forceinline__ void cstore(float*  C, size_t i, float v) { C[i] = v; }
__device__ __forceinline__ float sigf(float x) { return 1.f / (1.f + __expf(-x)); }

__global__ void zero_i(int* p) { if (threadIdx.x < 2) p[threadIdx.x] = 0; }
__global__ void f2h_kernel(const float* __restrict__ s, __half* __restrict__ d, int n) {
    for (int i = blockIdx.x * blockDim.x + threadIdx.x; i < n; i += gridDim.x * blockDim.x)
        d[i] = __float2half(s[i]);
}
// src fp32 [K][N] (row stride lds) -> dst fp16 [N][K]
__global__ void transpose_cvt(const float* __restrict__ src, int lds,
                              __half* __restrict__ dst, int K, int N) {
    __shared__ float tile[32][33];
    int kb = blockIdx.x * 32, nb = blockIdx.y * 32;
    #pragma unroll
    for (int i = threadIdx.y; i < 32; i += 8) {
        int k = kb + i, n = nb + threadIdx.x;
        tile[i][threadIdx.x] = (k < K && n < N) ? src[(size_t)k * lds + n] : 0.f;
    }
    __syncthreads();
    #pragma unroll
    for (int i = threadIdx.y; i < 32; i += 8) {
        int n = nb + i, k = kb + threadIdx.x;
        if (n < N && k < K) dst[(size_t)n * K + k] = __float2half(tile[threadIdx.x][i]);
    }
}

// ---------------- generic fp16 GEMM: C[M,N] = A[M,K] @ Bt[N,K]^T (+bias) ----------------
// CTA tile 128x64, K-tile 32, 4-stage cp.async pipeline, 256 thr, warp tile 32x32.
#define GAST (128*40)
#define GBST (64*40)
#define GEMM_SMEM ((4*(GAST+GBST))*2)

template <typename TOUT>
__global__ void __launch_bounds__(256) gemm16(
    const __half* __restrict__ A, int lda,
    const __half* __restrict__ Bt,
    TOUT* __restrict__ C, int ldc,
    const float* __restrict__ bias,
    int M, int N, int K)
{
    extern __shared__ __half sm[];
    __half* As = sm;
    __half* Bs = sm + 4*GAST;

    const int tid = threadIdx.x;
    const int bm = blockIdx.y * 128, bn = blockIdx.x * 64;
    const int wid = tid >> 5, lane = tid & 31;
    const int wr = (wid >> 1) * 32, wc = (wid & 1) * 32;
    const int r = lane >> 2, cl = lane & 3;

    float acc[2][4][4];
    #pragma unroll
    for (int i = 0; i < 2; ++i)
        #pragma unroll
        for (int j = 0; j < 4; ++j)
            #pragma unroll
            for (int k = 0; k < 4; ++k) acc[i][j][k] = 0.f;

    auto loadG = [&](int s, int kt) {
        #pragma unroll
        for (int i = 0; i < 2; ++i) {
            int idx = tid + i * 256;
            int row = idx >> 2, cc = idx & 3;
            cpa16(As + s*GAST + row*40 + cc*8,
                  A + (size_t)(bm + row) * lda + kt*32 + cc*8);
        }
        {
            int row = tid >> 2, cc = tid & 3;
            cpa16(Bs + s*GBST + row*40 + cc*8,
                  Bt + (size_t)(bn + row) * K + kt*32 + cc*8);
        }
    };

    const int ktiles = K >> 5;
    #pragma unroll
    for (int s = 0; s < 3; ++s) { if (s < ktiles) loadG(s, s); CPA_COMMIT(); }

    for (int kt = 0; kt < ktiles; ++kt) {
        cpa_wait<2>();
        __syncthreads();
        if (kt + 3 < ktiles) loadG((kt + 3) & 3, kt + 3);
        CPA_COMMIT();

        const __half* sA = As + (kt & 3) * GAST;
        const __half* sB = Bs + (kt & 3) * GBST;
        #pragma unroll
        for (int ks = 0; ks < 2; ++ks) {
            const int k0 = ks * 16;
            unsigned af[2][4], bf[4][2];
            #pragma unroll
            for (int mt = 0; mt < 2; ++mt) {
                af[mt][0] = *(const unsigned*)&sA[(wr + mt*16 + r    )*40 + k0 + 2*cl];
                af[mt][1] = *(const unsigned*)&sA[(wr + mt*16 + r + 8)*40 + k0 + 2*cl];
                af[mt][2] = *(const unsigned*)&sA[(wr + mt*16 + r    )*40 + k0 + 2*cl + 8];
                af[mt][3] = *(const unsigned*)&sA[(wr + mt*16 + r + 8)*40 + k0 + 2*cl + 8];
            }
            #pragma unroll
            for (int nt = 0; nt < 4; ++nt) {
                bf[nt][0] = *(const unsigned*)&sB[(wc + nt*8 + r)*40 + k0 + 2*cl];
                bf[nt][1] = *(const unsigned*)&sB[(wc + nt*8 + r)*40 + k0 + 2*cl + 8];
            }
            #pragma unroll
            for (int mt = 0; mt < 2; ++mt)
                #pragma unroll
                for (int nt = 0; nt < 4; ++nt)
                    mma16(acc[mt][nt], af[mt], bf[nt]);
        }
    }

    #pragma unroll
    for (int mt = 0; mt < 2; ++mt)
        #pragma unroll
        for (int nt = 0; nt < 4; ++nt) {
            const int row = bm + wr + mt*16 + r;
            const int col = bn + wc + nt*8 + 2*cl;
            const float b0 = bias ? bias[col]     : 0.f;
            const float b1 = bias ? bias[col + 1] : 0.f;
            cstore(C, (size_t)row * ldc + col,           acc[mt][nt][0] + b0);
            cstore(C, (size_t)row * ldc + col + 1,       acc[mt][nt][1] + b1);
            cstore(C, (size_t)(row + 8) * ldc + col,     acc[mt][nt][2] + b0);
            cstore(C, (size_t)(row + 8) * ldc + col + 1, acc[mt][nt][3] + b1);
        }
}

// ---------------- persistent LSTM layer kernel ----------------
// 128 CTAs (1/SM, co-resident). CTA bx owns hidden cols [bx*8, bx*8+8) of all 4
// gates (GEMM N=32, K=1024). W_h slice (64KB) resident in smem for all 256 steps.
// c-state lives in registers. Steps synced by global counter + acquire spin.
#define AST (128*72)
#define LSTM_SMEM ((32*1032 + 4*AST)*2)

__global__ void __launch_bounds__(256, 1) lstm_layer(
    const __half* __restrict__ WhT,    // [4096][1024]
    const float*  __restrict__ X,      // [T*128][4096]
    __half* __restrict__ H,            // [T*128][1024]
    int* __restrict__ ctr)
{
    extern __shared__ __half sm[];
    __half* Bs = sm;                   // 32 x 1032
    __half* As = sm + 32*1032;         // 4 stages x 128 x 72

    const int tid = threadIdx.x, lane = tid & 31, wid = tid >> 5;
    const int r = lane >> 2, cl = lane & 3;
    const int bx = blockIdx.x;
    const int wr = wid * 16;
    const int row0 = wr + r, row1 = row0 + 8;
    const int jj = 2 * cl;
    const int colg = bx * 8 + jj;

    // load W_h slice once: rows g*1024 + bx*8 + j  ->  Bs[g*8+j][0..1023]
    #pragma unroll
    for (int i = 0; i < 16; ++i) {
        int idx = tid + i * 256;            // 0..4095
        int n = idx >> 7, cc = idx & 127;
        int g = n >> 3, j = n & 7;
        cpa16(Bs + n*1032 + cc*8,
              WhT + (size_t)(g*1024 + bx*8 + j) * 1024 + cc*8);
    }
    CPA_COMMIT();
    cpa_wait<0>();
    __syncthreads();

    float c0 = 0.f, c1 = 0.f, c2 = 0.f, c3 = 0.f;

    auto loadA = [&](__half* dst, const __half* hsrc, int kt) {
        #pragma unroll
        for (int i = 0; i < 4; ++i) {
            int idx = tid + i * 256;        // 0..1023
            int row = idx >> 3, cc = idx & 7;
            cpa16(dst + row*72 + cc*8, hsrc + (size_t)row*1024 + kt*64 + cc*8);
        }
    };

    for (int t = 0; t < TT; ++t) {
        float acc[4][4];
        #pragma unroll
        for (int i = 0; i < 4; ++i)
            #pragma unroll
            for (int j = 0; j < 4; ++j) acc[i][j] = 0.f;

        if (t > 0) {
            const __half* hsrc = H + (size_t)(t - 1) * BB * NH;
            #pragma unroll
            for (int s = 0; s < 3; ++s) { loadA(As + s*AST, hsrc, s); CPA_COMMIT(); }

            #pragma unroll 1
            for (int kt = 0; kt < 16; ++kt) {
                cpa_wait<2>();
                __syncthreads();
                if (kt + 3 < 16) loadA(As + ((kt + 3) & 3) * AST, hsrc, kt + 3);
                CPA_COMMIT();

                const __half* sA = As + (kt & 3) * AST;
                #pragma unroll
                for (int ks = 0; ks < 4; ++ks) {
                    const int k0 = ks * 16;
                    unsigned af[4];
                    af[0] = *(const unsigned*)&sA[row0*72 + k0 + jj];
                    af[1] = *(const unsigned*)&sA[row1*72 + k0 + jj];
                    af[2] = *(const unsigned*)&sA[row0*72 + k0 + jj + 8];
                    af[3] = *(const unsigned*)&sA[row1*72 + k0 + jj + 8];
                    #pragma unroll
                    for (int nt = 0; nt < 4; ++nt) {
                        const __half* bp = Bs + (size_t)(nt*8 + r)*1032 + kt*64 + k0 + jj;
                        unsigned bf[2];
                        bf[0] = *(const unsigned*)bp;
                        bf[1] = *(const unsigned*)(bp + 8);
                        mma16(acc[nt], af, bf);
                    }
                }
            }
        }

        // gates + state update, all in registers
        const float* Xt = X + (size_t)t * (BB * G4);
        {
            const float* xb = Xt + (size_t)row0 * 4096 + colg;
            float2 xf = *(const float2*)(xb);
            float2 xi = *(const float2*)(xb + 1024);
            float2 xo = *(const float2*)(xb + 2048);
            float2 xg = *(const float2*)(xb + 3072);
            float f  = sigf(acc[0][0] + xf.x), ig  = sigf(acc[1][0] + xi.x);
            float o  = sigf(acc[2][0] + xo.x), gg  = tanhf(acc[3][0] + xg.x);
            c0 = f * c0 + ig * gg;
            float f1 = sigf(acc[0][1] + xf.y), ig1 = sigf(acc[1][1] + xi.y);
            float o1 = sigf(acc[2][1] + xo.y), gg1 = tanhf(acc[3][1] + xg.y);
            c1 = f1 * c1 + ig1 * gg1;
            __half2 hv = __floats2half2_rn(o * tanhf(c0), o1 * tanhf(c1));
            *(__half2*)&H[(size_t)t*BB*NH + (size_t)row0*1024 + colg] = hv;
        }
        {
            const float* xb = Xt + (size_t)row1 * 4096 + colg;
            float2 xf = *(const float2*)(xb);
            float2 xi = *(const float2*)(xb + 1024);
            float2 xo = *(const float2*)(xb + 2048);
            float2 xg = *(const float2*)(xb + 3072);
            float f  = sigf(acc[0][2] + xf.x), ig  = sigf(acc[1][2] + xi.x);
            float o  = sigf(acc[2][2] + xo.x), gg  = tanhf(acc[3][2] + xg.x);
            c2 = f * c2 + ig * gg;
            float f1 = sigf(acc[0][3] + xf.y), ig1 = sigf(acc[1][3] + xi.y);
            float o1 = sigf(acc[2][3] + xo.y), gg1 = tanhf(acc[3][3] + xg.y);
            c3 = f1 * c3 + ig1 * gg1;
            __half2 hv = __floats2half2_rn(o * tanhf(c2), o1 * tanhf(c3));
            *(__half2*)&H[(size_t)t*BB*NH + (size_t)row1*1024 + colg] = hv;
        }

        if (t + 1 < TT) {
            __threadfence();       // release h stores GPU-wide
            __syncthreads();       // all threads' stores fenced before arrive
            if (tid == 0) {
                atomicAdd(ctr, 1);
                const int target = 128 * (t + 1);
                int v;
                do {
                    asm volatile("ld.acquire.gpu.b32 %0, [%1];" : "=r"(v) : "l"(ctr));
                } while (v < target);
            }
            __syncthreads();       // broadcast acquire to whole CTA
        }
    }
}

// ---------------- launch ----------------
extern "C" void kernel_launch(void* const* d_in, const int* in_sizes, int n_in,
                              void* d_out, int out_size) {
    (void)in_sizes; (void)n_in; (void)out_size;
    const float* inputs = (const float*)d_in[0];
    const float* emb    = (const float*)d_in[1];
    const float* w0     = (const float*)d_in[2];
    const float* b0     = (const float*)d_in[3];
    const float* w1     = (const float*)d_in[4];
    const float* b1     = (const float*)d_in[5];
    const float* outw   = (const float*)d_in[6];
    const float* outb   = (const float*)d_in[7];
    float* out = (float*)d_out;

    __half *inph, *embs, *H0, *H1, *embT, *w0xT, *w0hT, *w1xT, *w1hT, *owT;
    float *X;
    int *ctr;
    cudaGetSymbolAddress((void**)&inph, g_inph);
    cudaGetSymbolAddress((void**)&embs, g_embs);
    cudaGetSymbolAddress((void**)&X,    g_X);
    cudaGetSymbolAddress((void**)&H0,   g_H0);
    cudaGetSymbolAddress((void**)&H1,   g_H1);
    cudaGetSymbolAddress((void**)&embT, g_embT);
    cudaGetSymbolAddress((void**)&w0xT, g_w0xT);
    cudaGetSymbolAddress((void**)&w0hT, g_w0hT);
    cudaGetSymbolAddress((void**)&w1xT, g_w1xT);
    cudaGetSymbolAddress((void**)&w1hT, g_w1hT);
    cudaGetSymbolAddress((void**)&owT,  g_owT);
    cudaGetSymbolAddress((void**)&ctr,  g_ctr);

    cudaFuncSetAttribute(lstm_layer,     cudaFuncAttributeMaxDynamicSharedMemorySize, LSTM_SMEM);
    cudaFuncSetAttribute(gemm16<float>,  cudaFuncAttributeMaxDynamicSharedMemorySize, GEMM_SMEM);
    cudaFuncSetAttribute(gemm16<__half>, cudaFuncAttributeMaxDynamicSharedMemorySize, GEMM_SMEM);

    // prep
    f2h_kernel<<<1024, 256>>>(inputs, inph, TB * VV);
    {
        dim3 blk(32, 8);
        transpose_cvt<<<dim3(VV/32, EE/32), blk>>>(emb,                EE, embT, VV, EE);
        transpose_cvt<<<dim3(EE/32, G4/32), blk>>>(w0,                 G4, w0xT, EE, G4);
        transpose_cvt<<<dim3(NH/32, G4/32), blk>>>(w0 + (size_t)EE*G4, G4, w0hT, NH, G4);
        transpose_cvt<<<dim3(NH/32, G4/32), blk>>>(w1,                 G4, w1xT, NH, G4);
        transpose_cvt<<<dim3(NH/32, G4/32), blk>>>(w1 + (size_t)NH*G4, G4, w1hT, NH, G4);
        transpose_cvt<<<dim3(NH/32, VV/32), blk>>>(outw,               VV, owT,  NH, VV);
    }
    zero_i<<<1, 32>>>(ctr);

    // embs = inputs @ emb
    gemm16<__half><<<dim3(EE/64, TB/128), 256, GEMM_SMEM>>>(inph, VV, embT, embs, EE, nullptr, TB, EE, VV);
    // X = embs @ W0x + b0
    gemm16<float><<<dim3(G4/64, TB/128), 256, GEMM_SMEM>>>(embs, EE, w0xT, X, G4, b0, TB, G4, EE);
    // layer 0 (persistent)
    lstm_layer<<<128, 256, LSTM_SMEM>>>(w0hT, X, H0, ctr);
    // X = H0 @ W1x + b1
    gemm16<float><<<dim3(G4/64, TB/128), 256, GEMM_SMEM>>>(H0, NH, w1xT, X, G4, b1, TB, G4, NH);
    // layer 1 (persistent)
    lstm_layer<<<128, 256, LSTM_SMEM>>>(w1hT, X, H1, ctr + 1);
    // logits = H1 @ out_w + out_b
    gemm16<float><<<dim3(VV/64, TB/128), 256, GEMM_SMEM>>>(H1, NH, owT, out, VV, outb, TB, VV, NH);
}